// round 7
// baseline (speedup 1.0000x reference)
#include <cuda_runtime.h>
#include <math.h>

// Problem constants (from reference): N=50000, F_IN=F_OUT=128, E=800000
#define FDIM 128
#define NMAX 50000

// Scratch for hi = spmm(G, input). 50000*128 floats = 25.6 MB.
// __device__ global (module-load allocation) — allowed under the alloc rules.
__device__ __align__(16) float g_hi[NMAX * FDIM];

// ---------------------------------------------------------------------------
// Kernel 1: init g_hi = (alpha / (1 - alpha)) * h0
// so that support = (1-alpha) * (hi_scatter + ratio*h0) = (1-alpha)*hi + alpha*h0
// ---------------------------------------------------------------------------
__global__ void init_hi_kernel(const float* __restrict__ h0,
                               const float* __restrict__ alpha_p,
                               int n_elems4) {
    float a = *alpha_p;
    float r = a / (1.0f - a);
    const float4* __restrict__ src = (const float4*)h0;
    float4* __restrict__ dst = (float4*)g_hi;
    for (int i = blockIdx.x * blockDim.x + threadIdx.x; i < n_elems4;
         i += gridDim.x * blockDim.x) {
        float4 v = src[i];
        v.x *= r; v.y *= r; v.z *= r; v.w *= r;
        dst[i] = v;
    }
}

// ---------------------------------------------------------------------------
// Kernel 2: SpMM scatter. One warp per edge.
// Each lane: gather 16B of input[col], scale by edge_val, vector-red into g_hi[row].
// red.global.add.v4.f32 (sm_90+) = 1 instruction per 16B instead of 4 atomicAdds.
// ---------------------------------------------------------------------------
__global__ void spmm_scatter_kernel(const float* __restrict__ x,
                                    const int* __restrict__ erow,
                                    const int* __restrict__ ecol,
                                    const float* __restrict__ eval,
                                    int E) {
    int gw = (blockIdx.x * blockDim.x + threadIdx.x) >> 5;
    int lane = threadIdx.x & 31;
    if (gw >= E) return;

    int row = erow[gw];
    int col = ecol[gw];
    float v = eval[gw];

    const float4* __restrict__ src = (const float4*)(x + (size_t)col * FDIM);
    float4 m = src[lane];
    m.x *= v; m.y *= v; m.z *= v; m.w *= v;

    float* dst = g_hi + (size_t)row * FDIM + lane * 4;
    asm volatile("red.global.add.v4.f32 [%0], {%1, %2, %3, %4};"
                 :: "l"(dst), "f"(m.x), "f"(m.y), "f"(m.z), "f"(m.w)
                 : "memory");
}

// ---------------------------------------------------------------------------
// Kernel 3: fused support + GEMM + epilogue.
//   S = (1-alpha) * g_hi                      (hi already carries the h0 term)
//   out = S @ (theta*W) + (1-theta)*S + input
// Block: 256 threads, 32 rows x 128 cols, K tiled by 32.
// Thread (ct = tid&31, rg = tid>>5): 4 rows x 4 cols register tile.
// ---------------------------------------------------------------------------
#define RB 32     // rows per block
#define KT 32     // K tile

__global__ __launch_bounds__(256, 4)
void gemm_epilogue_kernel(const float* __restrict__ x,
                          const float* __restrict__ W,
                          const float* __restrict__ lam_p,
                          const float* __restrict__ alpha_p,
                          const int* __restrict__ l_p,
                          float* __restrict__ out,
                          int n) {
    __shared__ float Wsh[KT * FDIM];   // 16 KB, scaled by theta
    __shared__ float Ssh[RB * FDIM];   // 16 KB, full support tile (reused in epilogue)

    const float lam = *lam_p;
    const float a = *alpha_p;
    const int l = *l_p;                       // first 4 LE bytes: ok for i32 or i64
    const float theta = logf(lam / (float)l + 1.0f);
    const float oma = 1.0f - a;
    const float omt = 1.0f - theta;

    const int tid = threadIdx.x;
    const int row0 = blockIdx.x * RB;

    // ---- Load S tile: RB*FDIM = 4096 floats = 1024 float4, 4 per thread ----
    const float4* __restrict__ hi4 = (const float4*)g_hi;
    #pragma unroll
    for (int i = 0; i < 4; i++) {
        int idx = tid + i * 256;         // float4 index within tile
        int r = idx >> 5;                // FDIM/4 = 32 float4 per row
        int c = idx & 31;
        int gr = row0 + r;
        float4 v = make_float4(0.f, 0.f, 0.f, 0.f);
        if (gr < n) v = hi4[(size_t)gr * 32 + c];
        v.x *= oma; v.y *= oma; v.z *= oma; v.w *= oma;
        ((float4*)Ssh)[idx] = v;
    }

    const int ct = tid & 31;    // column group: cols [4*ct, 4*ct+3]
    const int rg = tid >> 5;    // row group: rows  [4*rg, 4*rg+3] (local)

    float4 acc0 = make_float4(0.f, 0.f, 0.f, 0.f);
    float4 acc1 = make_float4(0.f, 0.f, 0.f, 0.f);
    float4 acc2 = make_float4(0.f, 0.f, 0.f, 0.f);
    float4 acc3 = make_float4(0.f, 0.f, 0.f, 0.f);

    const float4* __restrict__ W4 = (const float4*)W;

    #pragma unroll
    for (int kt = 0; kt < FDIM / KT; kt++) {
        // Load W tile (scaled by theta): KT*FDIM = 4096 floats = 1024 float4
        #pragma unroll
        for (int i = 0; i < 4; i++) {
            int idx = tid + i * 256;
            int r = idx >> 5;
            int c = idx & 31;
            float4 w = W4[(size_t)(kt * KT + r) * 32 + c];
            w.x *= theta; w.y *= theta; w.z *= theta; w.w *= theta;
            ((float4*)Wsh)[idx] = w;
        }
        __syncthreads();

        #pragma unroll
        for (int k = 0; k < KT; k++) {
            float4 w = ((const float4*)Wsh)[k * 32 + ct];  // conflict-free
            int kk = kt * KT + k;
            float s0 = Ssh[(rg * 4 + 0) * FDIM + kk];      // broadcast
            float s1 = Ssh[(rg * 4 + 1) * FDIM + kk];
            float s2 = Ssh[(rg * 4 + 2) * FDIM + kk];
            float s3 = Ssh[(rg * 4 + 3) * FDIM + kk];
            acc0.x = fmaf(s0, w.x, acc0.x); acc0.y = fmaf(s0, w.y, acc0.y);
            acc0.z = fmaf(s0, w.z, acc0.z); acc0.w = fmaf(s0, w.w, acc0.w);
            acc1.x = fmaf(s1, w.x, acc1.x); acc1.y = fmaf(s1, w.y, acc1.y);
            acc1.z = fmaf(s1, w.z, acc1.z); acc1.w = fmaf(s1, w.w, acc1.w);
            acc2.x = fmaf(s2, w.x, acc2.x); acc2.y = fmaf(s2, w.y, acc2.y);
            acc2.z = fmaf(s2, w.z, acc2.z); acc2.w = fmaf(s2, w.w, acc2.w);
            acc3.x = fmaf(s3, w.x, acc3.x); acc3.y = fmaf(s3, w.y, acc3.y);
            acc3.z = fmaf(s3, w.z, acc3.z); acc3.w = fmaf(s3, w.w, acc3.w);
        }
        __syncthreads();
    }

    // ---- Epilogue: out = acc + (1-theta)*S + input ----
    const float4* __restrict__ x4 = (const float4*)x;
    float4* __restrict__ out4 = (float4*)out;
    float4 accs[4] = {acc0, acc1, acc2, acc3};
    #pragma unroll
    for (int r = 0; r < 4; r++) {
        int lr = rg * 4 + r;
        int gr = row0 + lr;
        if (gr < n) {
            float4 s = ((const float4*)Ssh)[lr * 32 + ct];
            float4 xi = x4[(size_t)gr * 32 + ct];
            float4 o;
            o.x = accs[r].x + omt * s.x + xi.x;
            o.y = accs[r].y + omt * s.y + xi.y;
            o.z = accs[r].z + omt * s.z + xi.z;
            o.w = accs[r].w + omt * s.w + xi.w;
            out4[(size_t)gr * 32 + ct] = o;
        }
    }
}

// ---------------------------------------------------------------------------
// Launch. Inputs (metadata order):
//  0 input[N,128] f32   1 h0[N,128] f32   2 edge_row[E] i32   3 edge_col[E] i32
//  4 edge_val[E] f32    5 weight[128,128] f32
//  6 lamda f32[1]       7 alpha f32[1]    8 l (int scalar)
// ---------------------------------------------------------------------------
extern "C" void kernel_launch(void* const* d_in, const int* in_sizes, int n_in,
                              void* d_out, int out_size) {
    const float* x     = (const float*)d_in[0];
    const float* h0    = (const float*)d_in[1];
    const int*   erow  = (const int*)d_in[2];
    const int*   ecol  = (const int*)d_in[3];
    const float* eval  = (const float*)d_in[4];
    const float* W     = (const float*)d_in[5];
    const float* lam_p = (const float*)d_in[6];
    const float* alp_p = (const float*)d_in[7];
    const int*   l_p   = (const int*)d_in[8];
    float* out = (float*)d_out;

    int n = in_sizes[0] / FDIM;     // 50000
    int E = in_sizes[2];            // 800000

    // 1) hi := (alpha/(1-alpha)) * h0
    int n_elems4 = n * FDIM / 4;
    init_hi_kernel<<<592, 256>>>(h0, alp_p, n_elems4);

    // 2) scatter: one warp per edge, 8 edges per 256-thread block
    int sblocks = (E + 7) / 8;
    spmm_scatter_kernel<<<sblocks, 256>>>(x, erow, ecol, eval, E);

    // 3) fused support + GEMM + epilogue
    int gblocks = (n + RB - 1) / RB;
    gemm_epilogue_kernel<<<gblocks, 256>>>(x, W, lam_p, alp_p, l_p, out, n);
}

// round 8
// speedup vs baseline: 1.4619x; 1.4619x over previous
#include <cuda_runtime.h>
#include <math.h>

// Problem constants: N=50000, F_IN=F_OUT=128, E=800000
#define FDIM 128
#define NMAX 50000
#define CAP 64          // bucket capacity per row (avg degree 16, Poisson tail << CAP)
#define MAX_OVF 65536   // overflow edge list capacity (effectively never used)

// -------- device scratch (static globals: allowed; no runtime alloc) --------
__device__ __align__(16) float g_hi[NMAX * FDIM];                    // 25.6 MB: support
__device__ int g_count[NMAX];                                        // per-row degree
__device__ unsigned long long g_bucket[(size_t)NMAX * CAP];          // 25.6 MB: (val<<32)|col
__device__ int g_ovf_count;
__device__ int g_ovf_edges[MAX_OVF];

// ---------------------------------------------------------------------------
// K1: zero counters + overflow counter
// ---------------------------------------------------------------------------
__global__ void zero_counts_kernel(int n) {
    int i = blockIdx.x * blockDim.x + threadIdx.x;
    if (i < n) g_count[i] = 0;
    if (i == 0) g_ovf_count = 0;
}

// ---------------------------------------------------------------------------
// K2: bucket fill. One thread per edge: pos = atomicAdd(count[row]), write
// packed (val, col) 8B pair. Overflow edges go to a fallback list.
// ---------------------------------------------------------------------------
__global__ void fill_buckets_kernel(const int* __restrict__ erow,
                                    const int* __restrict__ ecol,
                                    const float* __restrict__ eval,
                                    int E) {
    int e = blockIdx.x * blockDim.x + threadIdx.x;
    if (e >= E) return;
    int row = erow[e];
    int pos = atomicAdd(&g_count[row], 1);
    if (pos < CAP) {
        unsigned long long packed =
            ((unsigned long long)__float_as_uint(eval[e]) << 32) | (unsigned)ecol[e];
        g_bucket[(size_t)row * CAP + pos] = packed;
    } else {
        int op = atomicAdd(&g_ovf_count, 1);
        if (op < MAX_OVF) g_ovf_edges[op] = e;
    }
}

// ---------------------------------------------------------------------------
// K3: gather SpMM + support, one warp per row.
// acc = sum_e val_e * x[col_e];  g_hi[row] = (1-a)*acc + a*h0[row]
// Lanes load bucket pairs coalesced, shfl-broadcast, gather x rows (L2-hit,
// 512B/warp coalesced), FMA into registers. No atomics.
// ---------------------------------------------------------------------------
__global__ __launch_bounds__(256)
void gather_support_kernel(const float* __restrict__ x,
                           const float* __restrict__ h0,
                           const float* __restrict__ alpha_p,
                           int n) {
    int warp = (blockIdx.x * blockDim.x + threadIdx.x) >> 5;
    int lane = threadIdx.x & 31;
    if (warp >= n) return;
    const int row = warp;

    int cnt = g_count[row];
    if (cnt > CAP) cnt = CAP;

    const unsigned long long* __restrict__ bkt = g_bucket + (size_t)row * CAP;
    const float4* __restrict__ x4 = (const float4*)x;

    float4 acc = make_float4(0.f, 0.f, 0.f, 0.f);
    for (int base = 0; base < cnt; base += 32) {
        int m = cnt - base; if (m > 32) m = 32;
        unsigned long long p = (lane < m) ? bkt[base + lane] : 0ULL;
        #pragma unroll 4
        for (int j = 0; j < m; j++) {
            unsigned long long pj = __shfl_sync(0xffffffffu, p, j);
            int col = (int)(unsigned)pj;
            float v = __uint_as_float((unsigned)(pj >> 32));
            float4 xv = __ldg(&x4[(size_t)col * 32 + lane]);
            acc.x = fmaf(v, xv.x, acc.x);
            acc.y = fmaf(v, xv.y, acc.y);
            acc.z = fmaf(v, xv.z, acc.z);
            acc.w = fmaf(v, xv.w, acc.w);
        }
    }

    float a = *alpha_p;
    float oma = 1.0f - a;
    float4 h = ((const float4*)h0)[(size_t)row * 32 + lane];
    float4 s;
    s.x = fmaf(oma, acc.x, a * h.x);
    s.y = fmaf(oma, acc.y, a * h.y);
    s.z = fmaf(oma, acc.z, a * h.z);
    s.w = fmaf(oma, acc.w, a * h.w);
    ((float4*)g_hi)[(size_t)row * 32 + lane] = s;
}

// ---------------------------------------------------------------------------
// K4: overflow fallback (normally 0 iterations). Adds (1-a)*val*x[col] into
// g_hi[row] via vector reduction AFTER support was written (support is linear
// in hi, so adding the scaled contribution post-hoc is exact).
// ---------------------------------------------------------------------------
__global__ void ovf_scatter_kernel(const float* __restrict__ x,
                                   const int* __restrict__ erow,
                                   const int* __restrict__ ecol,
                                   const float* __restrict__ eval,
                                   const float* __restrict__ alpha_p) {
    int cnt = g_ovf_count;
    if (cnt > MAX_OVF) cnt = MAX_OVF;
    if (cnt == 0) return;
    float oma = 1.0f - *alpha_p;
    int warps = (gridDim.x * blockDim.x) >> 5;
    int gw = (blockIdx.x * blockDim.x + threadIdx.x) >> 5;
    int lane = threadIdx.x & 31;
    const float4* __restrict__ x4 = (const float4*)x;
    for (int i = gw; i < cnt; i += warps) {
        int e = g_ovf_edges[i];
        int row = erow[e], col = ecol[e];
        float v = eval[e] * oma;
        float4 m = x4[(size_t)col * 32 + lane];
        m.x *= v; m.y *= v; m.z *= v; m.w *= v;
        float* dst = g_hi + (size_t)row * FDIM + lane * 4;
        asm volatile("red.global.add.v4.f32 [%0], {%1, %2, %3, %4};"
                     :: "l"(dst), "f"(m.x), "f"(m.y), "f"(m.z), "f"(m.w)
                     : "memory");
    }
}

// ---------------------------------------------------------------------------
// K5: fused GEMM + epilogue.  S = g_hi (already final support).
//   out = S @ (theta*W) + (1-theta)*S + input
// 256 threads, tile 64 rows x 128 cols, K tiled by 32.
// Thread (ct=tid&31, rg=tid>>5): 8 rows x 4 cols register tile.
// ---------------------------------------------------------------------------
#define RB 64
#define KT 32

__global__ __launch_bounds__(256)
void gemm_epilogue_kernel(const float* __restrict__ x,
                          const float* __restrict__ W,
                          const float* __restrict__ lam_p,
                          const int* __restrict__ l_p,
                          float* __restrict__ out,
                          int n) {
    __shared__ float Ssh[RB * FDIM];   // 32 KB
    __shared__ float Wsh[KT * FDIM];   // 16 KB

    const float theta = logf((*lam_p) / (float)(*l_p) + 1.0f);
    const float omt = 1.0f - theta;

    const int tid = threadIdx.x;
    const int row0 = blockIdx.x * RB;

    // Load S tile: 64*128 floats = 2048 float4, 8 per thread
    const float4* __restrict__ hi4 = (const float4*)g_hi;
    #pragma unroll
    for (int i = 0; i < 8; i++) {
        int idx = tid + i * 256;
        int r = idx >> 5;            // 32 float4 per row
        int c = idx & 31;
        int gr = row0 + r;
        float4 v = make_float4(0.f, 0.f, 0.f, 0.f);
        if (gr < n) v = hi4[(size_t)gr * 32 + c];
        ((float4*)Ssh)[idx] = v;
    }

    const int ct = tid & 31;   // cols [4*ct .. 4*ct+3]
    const int rg = tid >> 5;   // rows [8*rg .. 8*rg+7] (local)

    float4 acc[8];
    #pragma unroll
    for (int r = 0; r < 8; r++) acc[r] = make_float4(0.f, 0.f, 0.f, 0.f);

    const float4* __restrict__ W4 = (const float4*)W;

    #pragma unroll
    for (int kt = 0; kt < FDIM / KT; kt++) {
        // Load W tile scaled by theta: 32*128 floats = 1024 float4, 4/thread
        #pragma unroll
        for (int i = 0; i < 4; i++) {
            int idx = tid + i * 256;
            int r = idx >> 5;
            int c = idx & 31;
            float4 w = W4[(size_t)(kt * KT + r) * 32 + c];
            w.x *= theta; w.y *= theta; w.z *= theta; w.w *= theta;
            ((float4*)Wsh)[idx] = w;
        }
        __syncthreads();

        #pragma unroll
        for (int k = 0; k < KT; k++) {
            float4 w = ((const float4*)Wsh)[k * 32 + ct];   // 4-phase, conflict-free
            int kk = kt * KT + k;
            #pragma unroll
            for (int r = 0; r < 8; r++) {
                float s = Ssh[(rg * 8 + r) * FDIM + kk];    // warp-uniform broadcast
                acc[r].x = fmaf(s, w.x, acc[r].x);
                acc[r].y = fmaf(s, w.y, acc[r].y);
                acc[r].z = fmaf(s, w.z, acc[r].z);
                acc[r].w = fmaf(s, w.w, acc[r].w);
            }
        }
        __syncthreads();
    }

    // Epilogue: out = acc + (1-theta)*S + input
    const float4* __restrict__ x4 = (const float4*)x;
    float4* __restrict__ out4 = (float4*)out;
    #pragma unroll
    for (int r = 0; r < 8; r++) {
        int lr = rg * 8 + r;
        int gr = row0 + lr;
        if (gr < n) {
            float4 s = ((const float4*)Ssh)[lr * 32 + ct];
            float4 xi = x4[(size_t)gr * 32 + ct];
            float4 o;
            o.x = acc[r].x + omt * s.x + xi.x;
            o.y = acc[r].y + omt * s.y + xi.y;
            o.z = acc[r].z + omt * s.z + xi.z;
            o.w = acc[r].w + omt * s.w + xi.w;
            out4[(size_t)gr * 32 + ct] = o;
        }
    }
}

// ---------------------------------------------------------------------------
// Launch. Inputs (metadata order):
//  0 input[N,128] f32   1 h0[N,128] f32   2 edge_row[E] i32   3 edge_col[E] i32
//  4 edge_val[E] f32    5 weight[128,128] f32
//  6 lamda f32[1]       7 alpha f32[1]    8 l (int scalar)
// ---------------------------------------------------------------------------
extern "C" void kernel_launch(void* const* d_in, const int* in_sizes, int n_in,
                              void* d_out, int out_size) {
    const float* x     = (const float*)d_in[0];
    const float* h0    = (const float*)d_in[1];
    const int*   erow  = (const int*)d_in[2];
    const int*   ecol  = (const int*)d_in[3];
    const float* eval  = (const float*)d_in[4];
    const float* W     = (const float*)d_in[5];
    const float* lam_p = (const float*)d_in[6];
    const float* alp_p = (const float*)d_in[7];
    const int*   l_p   = (const int*)d_in[8];
    float* out = (float*)d_out;

    int n = in_sizes[0] / FDIM;     // 50000
    int E = in_sizes[2];            // 800000

    // 1) zero per-row counters
    zero_counts_kernel<<<(n + 255) / 256, 256>>>(n);

    // 2) bucket fill (one thread per edge)
    fill_buckets_kernel<<<(E + 255) / 256, 256>>>(erow, ecol, eval, E);

    // 3) gather SpMM + support (one warp per row, 8 warps/block)
    gather_support_kernel<<<(n + 7) / 8, 256>>>(x, h0, alp_p, n);

    // 4) overflow fallback (no-op when no overflow)
    ovf_scatter_kernel<<<8, 256>>>(x, erow, ecol, eval, alp_p);

    // 5) fused GEMM + epilogue
    gemm_epilogue_kernel<<<(n + RB - 1) / RB, 256>>>(x, W, lam_p, l_p, out, n);
}